// round 16
// baseline (speedup 1.0000x reference)
#include <cuda_runtime.h>
#include <cuda_bf16.h>
#include <cuda_fp16.h>
#include <math.h>
#include <stdint.h>

// Problem constants (shapes fixed by the dataset)
#define NN 50000
#define EE 800000
#define CC 128
#define HH 4
#define DD 32
#define QKV_COLS 384   // 3*C

#define SCAN_CHUNK 1024
#define NB_SCAN ((NN + SCAN_CHUNK - 1) / SCAN_CHUNK)   // 49

// GEMM: 3-term bf16 split D = ah*bh + al*bh + ah*bl as 12 pipelined K=32 chunks.
#define TM 128
#define TN 128
#define NCHUNK 12
#define CHUNK_A_BYTES 8192          // 128 rows x 64B
#define BUF_BYTES 16384             // A chunk + B chunk
#define SM_TOT (3 * BUF_BYTES)      // 49152, 3-deep ring -> 2 CTAs/SM

// ---------------- device scratch (no allocations allowed) ----------------
__device__ float g_qkv[NN * QKV_COLS];                        // q,k fp32 (v slots unused)
__device__ __align__(16) __half g_v16[NN * CC];               // fp16 V
__device__ __align__(16) __nv_bfloat16 g_a16[NN * 256];       // [m][hi(128)|lo(128)]
__device__ __align__(16) __nv_bfloat16 g_b16[QKV_COLS * 256];
__device__ __align__(16) float g_pw[NN * HH];                 // per-node per-head coord·w_h
__device__ int   g_offsets[NN + 1];
__device__ int   g_cursor[NN];
__device__ int   g_esrc[EE];
__device__ int   g_bsum[NB_SCAN + 1];
__device__ __align__(16) float g_rpeh[HH * 4];

__device__ __forceinline__ uint32_t smem_to_u32(const void* p) {
    uint32_t a;
    asm("{ .reg .u64 t; cvta.to.shared.u64 t, %1; cvt.u32.u64 %0, t; }" : "=r"(a) : "l"(p));
    return a;
}
#define LDMATRIX_X4(r0, r1, r2, r3, addr) \
    asm volatile("ldmatrix.sync.aligned.m8n8.x4.shared.b16 {%0,%1,%2,%3}, [%4];" \
                 : "=r"(r0), "=r"(r1), "=r"(r2), "=r"(r3) : "r"(addr))
#define MMA_BF16(d, a, b0, b1) \
    asm volatile("mma.sync.aligned.m16n8k16.row.col.f32.bf16.bf16.f32 " \
                 "{%0,%1,%2,%3}, {%4,%5,%6,%7}, {%8,%9}, {%0,%1,%2,%3};" \
                 : "+f"((d)[0]), "+f"((d)[1]), "+f"((d)[2]), "+f"((d)[3]) \
                 : "r"((a)[0]), "r"((a)[1]), "r"((a)[2]), "r"((a)[3]), \
                   "r"(b0), "r"(b1))
#define CP_ASYNC16(smem_addr, gptr, szbytes) \
    asm volatile("cp.async.cg.shared.global [%0], [%1], 16, %2;" \
                 :: "r"(smem_addr), "l"(gptr), "r"(szbytes) : "memory")
#define CP_COMMIT() asm volatile("cp.async.commit_group;" ::: "memory")

__device__ __forceinline__ uint32_t chunk_off(int r, int c) {
    return (uint32_t)((r >> 1) * 128 + (r & 1) * 64 + (((c ^ ((r >> 1) & 3)) & 3) << 4));
}

// ---------------- rpe collapse ----------------
__global__ void rpe_kernel(const float* __restrict__ rpe_w,
                           const float* __restrict__ rpe_b) {
    int t = threadIdx.x;
    if (t >= HH * 4) return;
    int h = t >> 2, p = t & 3;
    float s = 0.f;
    for (int d = 0; d < DD; d++) {
        int r = h * DD + d;
        s += (p < 3) ? rpe_w[r * 3 + p] : rpe_b[r];
    }
    g_rpeh[t] = s;
}

// ---------------- per-node per-head coord·w_h ----------------
__global__ void pw_kernel(const float* __restrict__ coord, int n) {
    int idx = blockIdx.x * blockDim.x + threadIdx.x;
    if (idx >= n * HH) return;
    int node = idx >> 2, h = idx & 3;
    float cx = coord[node * 3 + 0];
    float cy = coord[node * 3 + 1];
    float cz = coord[node * 3 + 2];
    float4 w = *reinterpret_cast<const float4*>(&g_rpeh[h * 4]);
    g_pw[idx] = cx * w.x + cy * w.y + cz * w.z;
}

// ---------------- zero degree counters ----------------
__global__ void zero_kernel(int n) {
    int i = blockIdx.x * blockDim.x + threadIdx.x;
    if (i < n) g_cursor[i] = 0;
}

// ---------------- fp32 -> bf16 hi/lo split ----------------
__global__ void conv_a_kernel(const float* __restrict__ feat, int n) {
    int idx = blockIdx.x * blockDim.x + threadIdx.x;
    if (idx >= n * CC) return;
    int m = idx >> 7, k = idx & 127;
    float x = feat[idx];
    __nv_bfloat16 h = __float2bfloat16(x);
    __nv_bfloat16 l = __float2bfloat16(x - __bfloat162float(h));
    g_a16[m * 256 + k] = h;
    g_a16[m * 256 + CC + k] = l;
}
__global__ void conv_b_kernel(const float* __restrict__ w) {
    int idx = blockIdx.x * blockDim.x + threadIdx.x;
    if (idx >= QKV_COLS * CC) return;
    int m = idx >> 7, k = idx & 127;
    float x = w[idx];
    __nv_bfloat16 h = __float2bfloat16(x);
    __nv_bfloat16 l = __float2bfloat16(x - __bfloat162float(h));
    g_b16[m * 256 + k] = h;
    g_b16[m * 256 + CC + k] = l;
}

// ---------------- cp.async-pipelined bf16 3-term split GEMM ----------------
__global__ __launch_bounds__(256, 2)
void mma_gemm_kernel(const float* __restrict__ bias, int M) {
    extern __shared__ char smem[];
    const uint32_t smbase = smem_to_u32(smem);
    const int tid = threadIdx.x;
    const int lane = tid & 31;
    const int wid = tid >> 5;
    const int warpM = wid >> 2;
    const int warpN = wid & 3;
    const int m0 = blockIdx.y * TM;
    const int n0 = blockIdx.x * TN;

    const int aidx[NCHUNK] = {0, 1, 2, 3, 4, 5, 6, 7, 0, 1, 2, 3}; // ah, al, ah
    const int bidx[NCHUNK] = {0, 1, 2, 3, 0, 1, 2, 3, 4, 5, 6, 7}; // bh, bh, bl

    const uint4* a4 = reinterpret_cast<const uint4*>(g_a16);
    const uint4* b4 = reinterpret_cast<const uint4*>(g_b16);

    const int sr0 = tid >> 2, sc0 = tid & 3;
    const int sr1 = (tid + 256) >> 2, sc1 = (tid + 256) & 3;
    const uint32_t soA0 = chunk_off(sr0, sc0), soA1 = chunk_off(sr1, sc1);

    auto ld_chunk = [&](int buf, int ac, int bc) {
        uint32_t base = smbase + (uint32_t)buf * BUF_BYTES;
        int szA0 = (m0 + sr0 < M) ? 16 : 0;
        int szA1 = (m0 + sr1 < M) ? 16 : 0;
        CP_ASYNC16(base + soA0, a4 + (size_t)(m0 + sr0) * 32 + ac * 4 + sc0, szA0);
        CP_ASYNC16(base + soA1, a4 + (size_t)(m0 + sr1) * 32 + ac * 4 + sc1, szA1);
        uint32_t baseB = base + CHUNK_A_BYTES;
        CP_ASYNC16(baseB + soA0, b4 + (size_t)(n0 + sr0) * 32 + bc * 4 + sc0, 16);
        CP_ASYNC16(baseB + soA1, b4 + (size_t)(n0 + sr1) * 32 + bc * 4 + sc1, 16);
        CP_COMMIT();
    };

    float acc[4][4][4];
#pragma unroll
    for (int mt = 0; mt < 4; mt++)
#pragma unroll
        for (int nt = 0; nt < 4; nt++)
#pragma unroll
            for (int c = 0; c < 4; c++) acc[mt][nt][c] = 0.f;

    const int arow_base = warpM * 64 + (lane & 15);
    const int brow_base = warpN * 32 + (lane & 15);
    const int chalf = lane >> 4;

    ld_chunk(0, aidx[0], bidx[0]);
    ld_chunk(1, aidx[1], bidx[1]);

#pragma unroll
    for (int t = 0; t < NCHUNK; t++) {
        if (t < NCHUNK - 1) asm volatile("cp.async.wait_group 1;" ::: "memory");
        else               asm volatile("cp.async.wait_group 0;" ::: "memory");
        __syncthreads();
        if (t + 2 < NCHUNK) ld_chunk((t + 2) % 3, aidx[t + 2], bidx[t + 2]);

        uint32_t bufA = smbase + (uint32_t)(t % 3) * BUF_BYTES;
        uint32_t bufB = bufA + CHUNK_A_BYTES;
#pragma unroll
        for (int ks2 = 0; ks2 < 2; ks2++) {
            int c = ks2 * 2 + chalf;
            uint32_t af[4][4];
#pragma unroll
            for (int mt = 0; mt < 4; mt++) {
                int r = arow_base + mt * 16;
                LDMATRIX_X4(af[mt][0], af[mt][1], af[mt][2], af[mt][3],
                            bufA + chunk_off(r, c));
            }
            uint32_t bf[2][4];
#pragma unroll
            for (int bt = 0; bt < 2; bt++) {
                int r = brow_base + bt * 16;
                LDMATRIX_X4(bf[bt][0], bf[bt][1], bf[bt][2], bf[bt][3],
                            bufB + chunk_off(r, c));
            }
#pragma unroll
            for (int mt = 0; mt < 4; mt++)
#pragma unroll
                for (int nt = 0; nt < 4; nt++) {
                    int bt = nt >> 1, sub = nt & 1;
                    MMA_BF16(acc[mt][nt], af[mt], bf[bt][sub], bf[bt][sub + 2]);
                }
        }
    }

    // ---- epilogue: add bias; q/k -> fp32 g_qkv, v -> fp16 g_v16 ----
    const int groupID = lane >> 2;
    const int tq = lane & 3;
    const bool is_v = (blockIdx.x == 2);
#pragma unroll
    for (int mt = 0; mt < 4; mt++) {
#pragma unroll
        for (int nt = 0; nt < 4; nt++) {
            int colL = warpN * 32 + nt * 8 + tq * 2;
            int col = n0 + colL;
            float2 b = *reinterpret_cast<const float2*>(&bias[col]);
            int r0 = m0 + warpM * 64 + mt * 16 + groupID;
            int r1 = r0 + 8;
            float2 o0 = make_float2(acc[mt][nt][0] + b.x, acc[mt][nt][1] + b.y);
            float2 o1 = make_float2(acc[mt][nt][2] + b.x, acc[mt][nt][3] + b.y);
            if (is_v) {
                if (r0 < M)
                    *reinterpret_cast<__half2*>(&g_v16[(size_t)r0 * CC + colL]) =
                        __floats2half2_rn(o0.x, o0.y);
                if (r1 < M)
                    *reinterpret_cast<__half2*>(&g_v16[(size_t)r1 * CC + colL]) =
                        __floats2half2_rn(o1.x, o1.y);
            } else {
                if (r0 < M)
                    *reinterpret_cast<float2*>(&g_qkv[(size_t)r0 * QKV_COLS + col]) = o0;
                if (r1 < M)
                    *reinterpret_cast<float2*>(&g_qkv[(size_t)r1 * QKV_COLS + col]) = o1;
            }
        }
    }
}

// ---------------- CSR build ----------------
__global__ void count_kernel(const int* __restrict__ dst, int e) {
    int i = blockIdx.x * blockDim.x + threadIdx.x;
    if (i < e) atomicAdd(&g_cursor[dst[i]], 1);
}

__device__ __forceinline__ int block_scan_inclusive(int v, int* warp_sums) {
    int lane = threadIdx.x & 31;
    int wid  = threadIdx.x >> 5;
    int x = v;
#pragma unroll
    for (int off = 1; off < 32; off <<= 1) {
        int y = __shfl_up_sync(0xffffffffu, x, off);
        if (lane >= off) x += y;
    }
    if (lane == 31) warp_sums[wid] = x;
    __syncthreads();
    if (wid == 0) {
        int ws = warp_sums[lane];
#pragma unroll
        for (int off = 1; off < 32; off <<= 1) {
            int y = __shfl_up_sync(0xffffffffu, ws, off);
            if (lane >= off) ws += y;
        }
        warp_sums[lane] = ws;
    }
    __syncthreads();
    int base = (wid > 0) ? warp_sums[wid - 1] : 0;
    return base + x;
}

__global__ void scan1_kernel(int n) {
    __shared__ int warp_sums[32];
    int i = blockIdx.x * SCAN_CHUNK + threadIdx.x;
    int v = (i < n) ? g_cursor[i] : 0;
    int inc = block_scan_inclusive(v, warp_sums);
    if (i < n) g_offsets[i] = inc - v;
    if (threadIdx.x == SCAN_CHUNK - 1) g_bsum[blockIdx.x] = inc;
}
__global__ void scan2_kernel(int nb) {
    __shared__ int warp_sums[32];
    int v = (threadIdx.x < (unsigned)nb) ? g_bsum[threadIdx.x] : 0;
    int inc = block_scan_inclusive(v, warp_sums);
    if (threadIdx.x < (unsigned)nb) g_bsum[threadIdx.x] = inc - v;
}
__global__ void scan3_kernel(int n, int e) {
    int i = blockIdx.x * SCAN_CHUNK + threadIdx.x;
    if (i < n) {
        int off = g_offsets[i] + g_bsum[blockIdx.x];
        g_offsets[i] = off;
        g_cursor[i]  = off;
    }
    if (i == 0) g_offsets[n] = e;
}
__global__ void fill_kernel(const int* __restrict__ dst,
                            const int* __restrict__ src, int e) {
    int i = blockIdx.x * blockDim.x + threadIdx.x;
    if (i < e) {
        int d = dst[i];
        int pos = atomicAdd(&g_cursor[d], 1);
        g_esrc[pos] = src[i];
    }
}

// ---------------- fused per-node attention ----------------
// no-max softmax, fp32 K, fp16 V, software-pipelined 4-edge batches (ping-pong regs)
#define LOAD_BATCH(S, base_) do { \
    _Pragma("unroll") \
    for (int j = 0; j < 4; j++) { \
        int idx_ = (base_) + j; if (idx_ >= end) idx_ = end - 1; \
        int sj_ = g_esrc[idx_]; \
        ss##S[j] = g_pw[sj_ * HH + h]; \
        kr##S[j] = *reinterpret_cast<const float4*>(&g_qkv[(size_t)sj_ * QKV_COLS + CC + lane * 4]); \
        vr##S[j] = *reinterpret_cast<const uint2*>(&g_v16[(size_t)sj_ * CC + lane * 4]); \
    } \
} while (0)

#define COMP_BATCH(S, base_) do { \
    float p_[4]; \
    _Pragma("unroll") \
    for (int j = 0; j < 4; j++) \
        p_[j] = q4.x * kr##S[j].x + q4.y * kr##S[j].y + q4.z * kr##S[j].z + q4.w * kr##S[j].w; \
    _Pragma("unroll") \
    for (int j = 0; j < 4; j++) p_[j] += __shfl_xor_sync(0xffffffffu, p_[j], 1); \
    _Pragma("unroll") \
    for (int j = 0; j < 4; j++) p_[j] += __shfl_xor_sync(0xffffffffu, p_[j], 2); \
    _Pragma("unroll") \
    for (int j = 0; j < 4; j++) p_[j] += __shfl_xor_sync(0xffffffffu, p_[j], 4); \
    _Pragma("unroll") \
    for (int j = 0; j < 4; j++) { \
        float ej_ = ((base_) + j < end) ? __expf(p_[j] + sd - ss##S[j]) : 0.f; \
        lsum += ej_; \
        float2 va_ = __half22float2(*reinterpret_cast<const __half2*>(&vr##S[j].x)); \
        float2 vb_ = __half22float2(*reinterpret_cast<const __half2*>(&vr##S[j].y)); \
        acc.x += ej_ * va_.x; acc.y += ej_ * va_.y; \
        acc.z += ej_ * vb_.x; acc.w += ej_ * vb_.y; \
    } \
} while (0)

__global__ void attn_kernel(float* __restrict__ out, int n) {
    int warp_in_block = threadIdx.x >> 5;
    int node = blockIdx.x * (blockDim.x >> 5) + warp_in_block;
    if (node >= n) return;
    int lane = threadIdx.x & 31;
    int h = lane >> 3;

    const float bh = g_rpeh[h * 4 + 3];
    const float sd = g_pw[node * HH + h] + bh;
    const float4 q4 = *reinterpret_cast<const float4*>(&g_qkv[node * QKV_COLS + lane * 4]);

    int beg = g_offsets[node];
    int end = g_offsets[node + 1];

    float lsum = 0.f;
    float4 acc = make_float4(0.f, 0.f, 0.f, 0.f);

    if (end > beg) {
        float4 krA[4], krB[4];
        uint2 vrA[4], vrB[4];
        float ssA[4], ssB[4];
        int nb = (end - beg + 3) >> 2;   // number of 4-edge batches
        int t = 0;
        LOAD_BATCH(A, beg);
        for (;;) {
            if (t + 1 < nb) LOAD_BATCH(B, beg + (t + 1) * 4);
            COMP_BATCH(A, beg + t * 4);
            t++;
            if (t >= nb) break;
            if (t + 1 < nb) LOAD_BATCH(A, beg + (t + 1) * 4);
            COMP_BATCH(B, beg + t * 4);
            t++;
            if (t >= nb) break;
        }
    }

    float inv = (lsum > 0.f) ? (1.f / lsum) : 0.f;
    float4 r = make_float4(acc.x * inv, acc.y * inv, acc.z * inv, acc.w * inv);
    *reinterpret_cast<float4*>(&out[node * CC + lane * 4]) = r;
}

// ---------------- launch ----------------
extern "C" void kernel_launch(void* const* d_in, const int* in_sizes, int n_in,
                              void* d_out, int out_size) {
    const float* feat   = (const float*)d_in[0];
    const float* coord  = (const float*)d_in[1];
    const int*   graph  = (const int*)d_in[2];
    const float* qkv_w  = (const float*)d_in[3];
    const float* qkv_b  = (const float*)d_in[4];
    const float* rpe_w  = (const float*)d_in[5];
    const float* rpe_b  = (const float*)d_in[6];
    float* out = (float*)d_out;

    int n = in_sizes[0] / CC;      // 50000
    int e = in_sizes[2] / 2;       // 800000
    if (n > NN) n = NN;
    if (e > EE) e = EE;

    const int* dst = graph;
    const int* src = graph + e;

    static cudaStream_t s2 = nullptr;
    static cudaEvent_t evFork = nullptr, evJoin = nullptr;
    if (!s2) {
        cudaStreamCreateWithFlags(&s2, cudaStreamNonBlocking);
        cudaEventCreateWithFlags(&evFork, cudaEventDisableTiming);
        cudaEventCreateWithFlags(&evJoin, cudaEventDisableTiming);
        cudaFuncSetAttribute(mma_gemm_kernel,
                             cudaFuncAttributeMaxDynamicSharedMemorySize, SM_TOT);
    }

    // fork: rpe/pw + CSR build on s2; conv + GEMM on main
    cudaEventRecord(evFork, 0);
    cudaStreamWaitEvent(s2, evFork, 0);

    {   // ---- s2: rpe + pw + CSR build by dst ----
        int tb = 256;
        rpe_kernel<<<1, 32, 0, s2>>>(rpe_w, rpe_b);
        pw_kernel<<<(n * HH + 255) / 256, 256, 0, s2>>>(coord, n);
        zero_kernel<<<(n + tb - 1) / tb, tb, 0, s2>>>(n);
        count_kernel<<<(e + tb - 1) / tb, tb, 0, s2>>>(dst, e);
        int nb = (n + SCAN_CHUNK - 1) / SCAN_CHUNK;
        scan1_kernel<<<nb, SCAN_CHUNK, 0, s2>>>(n);
        scan2_kernel<<<1, SCAN_CHUNK, 0, s2>>>(nb);
        scan3_kernel<<<nb, SCAN_CHUNK, 0, s2>>>(n, e);
        fill_kernel<<<(e + tb - 1) / tb, tb, 0, s2>>>(dst, src, e);
        cudaEventRecord(evJoin, s2);
    }

    {   // ---- main: conv + GEMM ----
        conv_a_kernel<<<(n * CC + 255) / 256, 256>>>(feat, n);
        conv_b_kernel<<<(QKV_COLS * CC + 255) / 256, 256>>>(qkv_w);
        dim3 grid(QKV_COLS / TN, (n + TM - 1) / TM);
        mma_gemm_kernel<<<grid, 256, SM_TOT>>>(qkv_b, n);
    }

    // join, then attention
    cudaStreamWaitEvent(0, evJoin, 0);
    {
        int warps_per_block = 8;
        int tb = warps_per_block * 32;
        int grid = (n + warps_per_block - 1) / warps_per_block;
        attn_kernel<<<grid, tb>>>(out, n);
    }
}

// round 17
// speedup vs baseline: 1.3521x; 1.3521x over previous
#include <cuda_runtime.h>
#include <cuda_bf16.h>
#include <cuda_fp16.h>
#include <math.h>
#include <stdint.h>

// Problem constants (shapes fixed by the dataset)
#define NN 50000
#define EE 800000
#define CC 128
#define HH 4
#define DD 32
#define QKV_COLS 384   // 3*C

#define SCAN_CHUNK 1024
#define NB_SCAN ((NN + SCAN_CHUNK - 1) / SCAN_CHUNK)   // 49

// GEMM: 3-term bf16 split D = ah*bh + al*bh + ah*bl as 12 pipelined K=32 chunks.
#define TM 128
#define TN 128
#define NCHUNK 12
#define CHUNK_A_BYTES 8192          // 128 rows x 64B
#define BUF_BYTES 16384             // A chunk + B chunk
#define SM_TOT (3 * BUF_BYTES)      // 49152, 3-deep ring -> 2 CTAs/SM

// ---------------- device scratch (no allocations allowed) ----------------
__device__ float g_qkv[NN * QKV_COLS];                        // q,k fp32 (v slots unused)
__device__ __align__(16) __half g_v16[NN * CC];               // fp16 V
__device__ __align__(16) __nv_bfloat16 g_a16[NN * 256];       // [m][hi(128)|lo(128)]
__device__ __align__(16) __nv_bfloat16 g_b16[QKV_COLS * 256];
__device__ __align__(16) float g_pw[NN * HH];                 // per-node per-head coord·w_h
__device__ int   g_offsets[NN + 1];
__device__ int   g_cursor[NN];
__device__ int   g_esrc[EE];
__device__ int   g_bsum[NB_SCAN + 1];
__device__ __align__(16) float g_rpeh[HH * 4];

__device__ __forceinline__ uint32_t smem_to_u32(const void* p) {
    uint32_t a;
    asm("{ .reg .u64 t; cvta.to.shared.u64 t, %1; cvt.u32.u64 %0, t; }" : "=r"(a) : "l"(p));
    return a;
}
#define LDMATRIX_X4(r0, r1, r2, r3, addr) \
    asm volatile("ldmatrix.sync.aligned.m8n8.x4.shared.b16 {%0,%1,%2,%3}, [%4];" \
                 : "=r"(r0), "=r"(r1), "=r"(r2), "=r"(r3) : "r"(addr))
#define MMA_BF16(d, a, b0, b1) \
    asm volatile("mma.sync.aligned.m16n8k16.row.col.f32.bf16.bf16.f32 " \
                 "{%0,%1,%2,%3}, {%4,%5,%6,%7}, {%8,%9}, {%0,%1,%2,%3};" \
                 : "+f"((d)[0]), "+f"((d)[1]), "+f"((d)[2]), "+f"((d)[3]) \
                 : "r"((a)[0]), "r"((a)[1]), "r"((a)[2]), "r"((a)[3]), \
                   "r"(b0), "r"(b1))
#define CP_ASYNC16(smem_addr, gptr, szbytes) \
    asm volatile("cp.async.cg.shared.global [%0], [%1], 16, %2;" \
                 :: "r"(smem_addr), "l"(gptr), "r"(szbytes) : "memory")
#define CP_COMMIT() asm volatile("cp.async.commit_group;" ::: "memory")

__device__ __forceinline__ uint32_t chunk_off(int r, int c) {
    return (uint32_t)((r >> 1) * 128 + (r & 1) * 64 + (((c ^ ((r >> 1) & 3)) & 3) << 4));
}

// ---------------- rpe collapse ----------------
__global__ void rpe_kernel(const float* __restrict__ rpe_w,
                           const float* __restrict__ rpe_b) {
    int t = threadIdx.x;
    if (t >= HH * 4) return;
    int h = t >> 2, p = t & 3;
    float s = 0.f;
    for (int d = 0; d < DD; d++) {
        int r = h * DD + d;
        s += (p < 3) ? rpe_w[r * 3 + p] : rpe_b[r];
    }
    g_rpeh[t] = s;
}

// ---------------- per-node per-head coord·w_h ----------------
__global__ void pw_kernel(const float* __restrict__ coord, int n) {
    int idx = blockIdx.x * blockDim.x + threadIdx.x;
    if (idx >= n * HH) return;
    int node = idx >> 2, h = idx & 3;
    float cx = coord[node * 3 + 0];
    float cy = coord[node * 3 + 1];
    float cz = coord[node * 3 + 2];
    float4 w = *reinterpret_cast<const float4*>(&g_rpeh[h * 4]);
    g_pw[idx] = cx * w.x + cy * w.y + cz * w.z;
}

// ---------------- zero degree counters ----------------
__global__ void zero_kernel(int n) {
    int i = blockIdx.x * blockDim.x + threadIdx.x;
    if (i < n) g_cursor[i] = 0;
}

// ---------------- fp32 -> bf16 hi/lo split ----------------
__global__ void conv_a_kernel(const float* __restrict__ feat, int n) {
    int idx = blockIdx.x * blockDim.x + threadIdx.x;
    if (idx >= n * CC) return;
    int m = idx >> 7, k = idx & 127;
    float x = feat[idx];
    __nv_bfloat16 h = __float2bfloat16(x);
    __nv_bfloat16 l = __float2bfloat16(x - __bfloat162float(h));
    g_a16[m * 256 + k] = h;
    g_a16[m * 256 + CC + k] = l;
}
__global__ void conv_b_kernel(const float* __restrict__ w) {
    int idx = blockIdx.x * blockDim.x + threadIdx.x;
    if (idx >= QKV_COLS * CC) return;
    int m = idx >> 7, k = idx & 127;
    float x = w[idx];
    __nv_bfloat16 h = __float2bfloat16(x);
    __nv_bfloat16 l = __float2bfloat16(x - __bfloat162float(h));
    g_b16[m * 256 + k] = h;
    g_b16[m * 256 + CC + k] = l;
}

// ---------------- cp.async-pipelined bf16 3-term split GEMM ----------------
__global__ __launch_bounds__(256, 2)
void mma_gemm_kernel(const float* __restrict__ bias, int M) {
    extern __shared__ char smem[];
    const uint32_t smbase = smem_to_u32(smem);
    const int tid = threadIdx.x;
    const int lane = tid & 31;
    const int wid = tid >> 5;
    const int warpM = wid >> 2;
    const int warpN = wid & 3;
    const int m0 = blockIdx.y * TM;
    const int n0 = blockIdx.x * TN;

    const int aidx[NCHUNK] = {0, 1, 2, 3, 4, 5, 6, 7, 0, 1, 2, 3}; // ah, al, ah
    const int bidx[NCHUNK] = {0, 1, 2, 3, 0, 1, 2, 3, 4, 5, 6, 7}; // bh, bh, bl

    const uint4* a4 = reinterpret_cast<const uint4*>(g_a16);
    const uint4* b4 = reinterpret_cast<const uint4*>(g_b16);

    const int sr0 = tid >> 2, sc0 = tid & 3;
    const int sr1 = (tid + 256) >> 2, sc1 = (tid + 256) & 3;
    const uint32_t soA0 = chunk_off(sr0, sc0), soA1 = chunk_off(sr1, sc1);

    auto ld_chunk = [&](int buf, int ac, int bc) {
        uint32_t base = smbase + (uint32_t)buf * BUF_BYTES;
        int szA0 = (m0 + sr0 < M) ? 16 : 0;
        int szA1 = (m0 + sr1 < M) ? 16 : 0;
        CP_ASYNC16(base + soA0, a4 + (size_t)(m0 + sr0) * 32 + ac * 4 + sc0, szA0);
        CP_ASYNC16(base + soA1, a4 + (size_t)(m0 + sr1) * 32 + ac * 4 + sc1, szA1);
        uint32_t baseB = base + CHUNK_A_BYTES;
        CP_ASYNC16(baseB + soA0, b4 + (size_t)(n0 + sr0) * 32 + bc * 4 + sc0, 16);
        CP_ASYNC16(baseB + soA1, b4 + (size_t)(n0 + sr1) * 32 + bc * 4 + sc1, 16);
        CP_COMMIT();
    };

    float acc[4][4][4];
#pragma unroll
    for (int mt = 0; mt < 4; mt++)
#pragma unroll
        for (int nt = 0; nt < 4; nt++)
#pragma unroll
            for (int c = 0; c < 4; c++) acc[mt][nt][c] = 0.f;

    const int arow_base = warpM * 64 + (lane & 15);
    const int brow_base = warpN * 32 + (lane & 15);
    const int chalf = lane >> 4;

    ld_chunk(0, aidx[0], bidx[0]);
    ld_chunk(1, aidx[1], bidx[1]);

#pragma unroll
    for (int t = 0; t < NCHUNK; t++) {
        if (t < NCHUNK - 1) asm volatile("cp.async.wait_group 1;" ::: "memory");
        else               asm volatile("cp.async.wait_group 0;" ::: "memory");
        __syncthreads();
        if (t + 2 < NCHUNK) ld_chunk((t + 2) % 3, aidx[t + 2], bidx[t + 2]);

        uint32_t bufA = smbase + (uint32_t)(t % 3) * BUF_BYTES;
        uint32_t bufB = bufA + CHUNK_A_BYTES;
#pragma unroll
        for (int ks2 = 0; ks2 < 2; ks2++) {
            int c = ks2 * 2 + chalf;
            uint32_t af[4][4];
#pragma unroll
            for (int mt = 0; mt < 4; mt++) {
                int r = arow_base + mt * 16;
                LDMATRIX_X4(af[mt][0], af[mt][1], af[mt][2], af[mt][3],
                            bufA + chunk_off(r, c));
            }
            uint32_t bf[2][4];
#pragma unroll
            for (int bt = 0; bt < 2; bt++) {
                int r = brow_base + bt * 16;
                LDMATRIX_X4(bf[bt][0], bf[bt][1], bf[bt][2], bf[bt][3],
                            bufB + chunk_off(r, c));
            }
#pragma unroll
            for (int mt = 0; mt < 4; mt++)
#pragma unroll
                for (int nt = 0; nt < 4; nt++) {
                    int bt = nt >> 1, sub = nt & 1;
                    MMA_BF16(acc[mt][nt], af[mt], bf[bt][sub], bf[bt][sub + 2]);
                }
        }
    }

    // ---- epilogue: add bias; q/k -> fp32 g_qkv, v -> fp16 g_v16 ----
    const int groupID = lane >> 2;
    const int tq = lane & 3;
    const bool is_v = (blockIdx.x == 2);
#pragma unroll
    for (int mt = 0; mt < 4; mt++) {
#pragma unroll
        for (int nt = 0; nt < 4; nt++) {
            int colL = warpN * 32 + nt * 8 + tq * 2;
            int col = n0 + colL;
            float2 b = *reinterpret_cast<const float2*>(&bias[col]);
            int r0 = m0 + warpM * 64 + mt * 16 + groupID;
            int r1 = r0 + 8;
            float2 o0 = make_float2(acc[mt][nt][0] + b.x, acc[mt][nt][1] + b.y);
            float2 o1 = make_float2(acc[mt][nt][2] + b.x, acc[mt][nt][3] + b.y);
            if (is_v) {
                if (r0 < M)
                    *reinterpret_cast<__half2*>(&g_v16[(size_t)r0 * CC + colL]) =
                        __floats2half2_rn(o0.x, o0.y);
                if (r1 < M)
                    *reinterpret_cast<__half2*>(&g_v16[(size_t)r1 * CC + colL]) =
                        __floats2half2_rn(o1.x, o1.y);
            } else {
                if (r0 < M)
                    *reinterpret_cast<float2*>(&g_qkv[(size_t)r0 * QKV_COLS + col]) = o0;
                if (r1 < M)
                    *reinterpret_cast<float2*>(&g_qkv[(size_t)r1 * QKV_COLS + col]) = o1;
            }
        }
    }
}

// ---------------- CSR build ----------------
__global__ void count_kernel(const int* __restrict__ dst, int e) {
    int i = blockIdx.x * blockDim.x + threadIdx.x;
    if (i < e) atomicAdd(&g_cursor[dst[i]], 1);
}

__device__ __forceinline__ int block_scan_inclusive(int v, int* warp_sums) {
    int lane = threadIdx.x & 31;
    int wid  = threadIdx.x >> 5;
    int x = v;
#pragma unroll
    for (int off = 1; off < 32; off <<= 1) {
        int y = __shfl_up_sync(0xffffffffu, x, off);
        if (lane >= off) x += y;
    }
    if (lane == 31) warp_sums[wid] = x;
    __syncthreads();
    if (wid == 0) {
        int ws = warp_sums[lane];
#pragma unroll
        for (int off = 1; off < 32; off <<= 1) {
            int y = __shfl_up_sync(0xffffffffu, ws, off);
            if (lane >= off) ws += y;
        }
        warp_sums[lane] = ws;
    }
    __syncthreads();
    int base = (wid > 0) ? warp_sums[wid - 1] : 0;
    return base + x;
}

__global__ void scan1_kernel(int n) {
    __shared__ int warp_sums[32];
    int i = blockIdx.x * SCAN_CHUNK + threadIdx.x;
    int v = (i < n) ? g_cursor[i] : 0;
    int inc = block_scan_inclusive(v, warp_sums);
    if (i < n) g_offsets[i] = inc - v;
    if (threadIdx.x == SCAN_CHUNK - 1) g_bsum[blockIdx.x] = inc;
}
__global__ void scan2_kernel(int nb) {
    __shared__ int warp_sums[32];
    int v = (threadIdx.x < (unsigned)nb) ? g_bsum[threadIdx.x] : 0;
    int inc = block_scan_inclusive(v, warp_sums);
    if (threadIdx.x < (unsigned)nb) g_bsum[threadIdx.x] = inc - v;
}
__global__ void scan3_kernel(int n, int e) {
    int i = blockIdx.x * SCAN_CHUNK + threadIdx.x;
    if (i < n) {
        int off = g_offsets[i] + g_bsum[blockIdx.x];
        g_offsets[i] = off;
        g_cursor[i]  = off;
    }
    if (i == 0) g_offsets[n] = e;
}
__global__ void fill_kernel(const int* __restrict__ dst,
                            const int* __restrict__ src, int e) {
    int i = blockIdx.x * blockDim.x + threadIdx.x;
    if (i < e) {
        int d = dst[i];
        int pos = atomicAdd(&g_cursor[d], 1);
        g_esrc[pos] = src[i];
    }
}

// ---------------- fused per-node attention (no-max softmax, fp32 K, fp16 V, unroll 4) ----------------
__global__ void attn_kernel(float* __restrict__ out, int n) {
    int warp_in_block = threadIdx.x >> 5;
    int node = blockIdx.x * (blockDim.x >> 5) + warp_in_block;
    if (node >= n) return;
    int lane = threadIdx.x & 31;
    int h = lane >> 3;

    const float bh = g_rpeh[h * 4 + 3];
    const float sd = g_pw[node * HH + h] + bh;     // dst-side rpe term (incl bias)
    const float4 q4 = *reinterpret_cast<const float4*>(&g_qkv[node * QKV_COLS + lane * 4]);

    int beg = g_offsets[node];
    int end = g_offsets[node + 1];

    float lsum = 0.f;
    float4 acc = make_float4(0.f, 0.f, 0.f, 0.f);

    int i = beg;
    for (; i + 3 < end; i += 4) {
        int s0 = g_esrc[i];
        int s1 = g_esrc[i + 1];
        int s2 = g_esrc[i + 2];
        int s3 = g_esrc[i + 3];
        const float4 k0 = *reinterpret_cast<const float4*>(&g_qkv[s0 * QKV_COLS + CC + lane * 4]);
        const float4 k1 = *reinterpret_cast<const float4*>(&g_qkv[s1 * QKV_COLS + CC + lane * 4]);
        const float4 k2 = *reinterpret_cast<const float4*>(&g_qkv[s2 * QKV_COLS + CC + lane * 4]);
        const float4 k3 = *reinterpret_cast<const float4*>(&g_qkv[s3 * QKV_COLS + CC + lane * 4]);
        const uint2 vr0 = *reinterpret_cast<const uint2*>(&g_v16[(size_t)s0 * CC + lane * 4]);
        const uint2 vr1 = *reinterpret_cast<const uint2*>(&g_v16[(size_t)s1 * CC + lane * 4]);
        const uint2 vr2 = *reinterpret_cast<const uint2*>(&g_v16[(size_t)s2 * CC + lane * 4]);
        const uint2 vr3 = *reinterpret_cast<const uint2*>(&g_v16[(size_t)s3 * CC + lane * 4]);
        float ss0 = g_pw[s0 * HH + h];
        float ss1 = g_pw[s1 * HH + h];
        float ss2 = g_pw[s2 * HH + h];
        float ss3 = g_pw[s3 * HH + h];

        float p0 = q4.x * k0.x + q4.y * k0.y + q4.z * k0.z + q4.w * k0.w;
        float p1 = q4.x * k1.x + q4.y * k1.y + q4.z * k1.z + q4.w * k1.w;
        float p2 = q4.x * k2.x + q4.y * k2.y + q4.z * k2.z + q4.w * k2.w;
        float p3 = q4.x * k3.x + q4.y * k3.y + q4.z * k3.z + q4.w * k3.w;
        p0 += __shfl_xor_sync(0xffffffffu, p0, 1);
        p1 += __shfl_xor_sync(0xffffffffu, p1, 1);
        p2 += __shfl_xor_sync(0xffffffffu, p2, 1);
        p3 += __shfl_xor_sync(0xffffffffu, p3, 1);
        p0 += __shfl_xor_sync(0xffffffffu, p0, 2);
        p1 += __shfl_xor_sync(0xffffffffu, p1, 2);
        p2 += __shfl_xor_sync(0xffffffffu, p2, 2);
        p3 += __shfl_xor_sync(0xffffffffu, p3, 2);
        p0 += __shfl_xor_sync(0xffffffffu, p0, 4);
        p1 += __shfl_xor_sync(0xffffffffu, p1, 4);
        p2 += __shfl_xor_sync(0xffffffffu, p2, 4);
        p3 += __shfl_xor_sync(0xffffffffu, p3, 4);

        float e0 = __expf(p0 + sd - ss0);
        float e1 = __expf(p1 + sd - ss1);
        float e2 = __expf(p2 + sd - ss2);
        float e3 = __expf(p3 + sd - ss3);
        lsum += (e0 + e1) + (e2 + e3);

        float2 v0a = __half22float2(*reinterpret_cast<const __half2*>(&vr0.x));
        float2 v0b = __half22float2(*reinterpret_cast<const __half2*>(&vr0.y));
        float2 v1a = __half22float2(*reinterpret_cast<const __half2*>(&vr1.x));
        float2 v1b = __half22float2(*reinterpret_cast<const __half2*>(&vr1.y));
        float2 v2a = __half22float2(*reinterpret_cast<const __half2*>(&vr2.x));
        float2 v2b = __half22float2(*reinterpret_cast<const __half2*>(&vr2.y));
        float2 v3a = __half22float2(*reinterpret_cast<const __half2*>(&vr3.x));
        float2 v3b = __half22float2(*reinterpret_cast<const __half2*>(&vr3.y));
        acc.x += (e0 * v0a.x + e1 * v1a.x) + (e2 * v2a.x + e3 * v3a.x);
        acc.y += (e0 * v0a.y + e1 * v1a.y) + (e2 * v2a.y + e3 * v3a.y);
        acc.z += (e0 * v0b.x + e1 * v1b.x) + (e2 * v2b.x + e3 * v3b.x);
        acc.w += (e0 * v0b.y + e1 * v1b.y) + (e2 * v2b.y + e3 * v3b.y);
    }
    for (; i < end; i++) {
        int s0 = g_esrc[i];
        const float4 k0 = *reinterpret_cast<const float4*>(&g_qkv[s0 * QKV_COLS + CC + lane * 4]);
        const uint2 vr0 = *reinterpret_cast<const uint2*>(&g_v16[(size_t)s0 * CC + lane * 4]);
        float ss0 = g_pw[s0 * HH + h];
        float p0 = q4.x * k0.x + q4.y * k0.y + q4.z * k0.z + q4.w * k0.w;
        p0 += __shfl_xor_sync(0xffffffffu, p0, 1);
        p0 += __shfl_xor_sync(0xffffffffu, p0, 2);
        p0 += __shfl_xor_sync(0xffffffffu, p0, 4);
        float e0 = __expf(p0 + sd - ss0);
        lsum += e0;
        float2 v0a = __half22float2(*reinterpret_cast<const __half2*>(&vr0.x));
        float2 v0b = __half22float2(*reinterpret_cast<const __half2*>(&vr0.y));
        acc.x += e0 * v0a.x;
        acc.y += e0 * v0a.y;
        acc.z += e0 * v0b.x;
        acc.w += e0 * v0b.y;
    }

    float inv = (lsum > 0.f) ? (1.f / lsum) : 0.f;
    float4 r = make_float4(acc.x * inv, acc.y * inv, acc.z * inv, acc.w * inv);
    *reinterpret_cast<float4*>(&out[node * CC + lane * 4]) = r;
}

// ---------------- launch ----------------
extern "C" void kernel_launch(void* const* d_in, const int* in_sizes, int n_in,
                              void* d_out, int out_size) {
    const float* feat   = (const float*)d_in[0];
    const float* coord  = (const float*)d_in[1];
    const int*   graph  = (const int*)d_in[2];
    const float* qkv_w  = (const float*)d_in[3];
    const float* qkv_b  = (const float*)d_in[4];
    const float* rpe_w  = (const float*)d_in[5];
    const float* rpe_b  = (const float*)d_in[6];
    float* out = (float*)d_out;

    int n = in_sizes[0] / CC;      // 50000
    int e = in_sizes[2] / 2;       // 800000
    if (n > NN) n = NN;
    if (e > EE) e = EE;

    const int* dst = graph;
    const int* src = graph + e;

    static cudaStream_t s2 = nullptr;
    static cudaEvent_t evFork = nullptr, evJoin = nullptr;
    if (!s2) {
        cudaStreamCreateWithFlags(&s2, cudaStreamNonBlocking);
        cudaEventCreateWithFlags(&evFork, cudaEventDisableTiming);
        cudaEventCreateWithFlags(&evJoin, cudaEventDisableTiming);
        cudaFuncSetAttribute(mma_gemm_kernel,
                             cudaFuncAttributeMaxDynamicSharedMemorySize, SM_TOT);
    }

    // fork: rpe/pw + CSR build on s2; conv + GEMM on main
    cudaEventRecord(evFork, 0);
    cudaStreamWaitEvent(s2, evFork, 0);

    {   // ---- s2: rpe + pw + CSR build by dst ----
        int tb = 256;
        rpe_kernel<<<1, 32, 0, s2>>>(rpe_w, rpe_b);
        pw_kernel<<<(n * HH + 255) / 256, 256, 0, s2>>>(coord, n);
        zero_kernel<<<(n + tb - 1) / tb, tb, 0, s2>>>(n);
        count_kernel<<<(e + tb - 1) / tb, tb, 0, s2>>>(dst, e);
        int nb = (n + SCAN_CHUNK - 1) / SCAN_CHUNK;
        scan1_kernel<<<nb, SCAN_CHUNK, 0, s2>>>(n);
        scan2_kernel<<<1, SCAN_CHUNK, 0, s2>>>(nb);
        scan3_kernel<<<nb, SCAN_CHUNK, 0, s2>>>(n, e);
        fill_kernel<<<(e + tb - 1) / tb, tb, 0, s2>>>(dst, src, e);
        cudaEventRecord(evJoin, s2);
    }

    {   // ---- main: conv + GEMM ----
        conv_a_kernel<<<(n * CC + 255) / 256, 256>>>(feat, n);
        conv_b_kernel<<<(QKV_COLS * CC + 255) / 256, 256>>>(qkv_w);
        dim3 grid(QKV_COLS / TN, (n + TM - 1) / TM);
        mma_gemm_kernel<<<grid, 256, SM_TOT>>>(qkv_b, n);
    }

    // join, then attention
    cudaStreamWaitEvent(0, evJoin, 0);
    {
        int warps_per_block = 8;
        int tb = warps_per_block * 32;
        int grid = (n + warps_per_block - 1) / warps_per_block;
        attn_kernel<<<grid, tb>>>(out, n);
    }
}